// round 7
// baseline (speedup 1.0000x reference)
#include <cuda_runtime.h>

#define N_NODES 500000
#define N_EDGES 16000000
#define FULL 0xffffffffu
#define CAP_LOG 6                              // 64 slots per bucket
#define CAP (1 << CAP_LOG)

// ---------------- device scratch (static; no allocation) ----------------
// counts: [0,N) cin (gather in-deg), [N,2N) cout (scatter out-deg), [2N,3N) csd (scatter in-deg)
__device__ int   g_cnt3[3 * N_NODES];
__device__ int   g_col [(size_t)N_NODES * CAP];  // CSR buckets (gather edges, by dst)
__device__ int   g_colc[(size_t)N_NODES * CAP];  // CSC buckets (scatter edges, by src)
__device__ float g_pa[(size_t)N_NODES * 8];      // projected features (32B records)
__device__ float g_pb[(size_t)N_NODES * 8];
__device__ float g_sa[(size_t)N_NODES * 8];      // precomputed self terms
__device__ float g_sb[(size_t)N_NODES * 8];
__device__ float g_acc0[(size_t)N_NODES * 8];    // scatter accumulators (32B records)
__device__ float g_acc1[(size_t)N_NODES * 8];
__device__ float g_acc9[N_NODES];                // scalar accumulator for final layer

__device__ __forceinline__ void red_add_v4(float* p, float a, float b, float c, float d) {
    asm volatile("red.global.add.v4.f32 [%0], {%1,%2,%3,%4};"
                 :: "l"(p), "f"(a), "f"(b), "f"(c), "f"(d) : "memory");
}
__device__ __forceinline__ void red_add_f32(float* p, float v) {
    asm volatile("red.global.add.f32 [%0], %1;" :: "l"(p), "f"(v) : "memory");
}

// ---------------- single-pass routed build: 5/8 gather (CSR), 3/8 scatter (CSC) ----------------
__global__ void k_fill(const int* __restrict__ ei, int E) {
    int e4 = (blockIdx.x * blockDim.x + threadIdx.x) * 4;
    if (e4 >= E) return;
    int4 d = *reinterpret_cast<const int4*>(ei + E + e4);  // dst
    int4 s = *reinterpret_cast<const int4*>(ei + e4);      // src
    int dd[4] = {d.x, d.y, d.z, d.w};
    int ss[4] = {s.x, s.y, s.z, s.w};
    #pragma unroll
    for (int k = 0; k < 4; ++k) {
        int idx = e4 + k;
        if ((idx & 7) < 5) {                               // gather edge -> CSR by dst
            int pos = atomicAdd(&g_cnt3[dd[k]], 1);
            if (pos < CAP) g_col[((size_t)dd[k] << CAP_LOG) + pos] = ss[k];
        } else {                                           // scatter edge -> CSC by src
            int pos = atomicAdd(&g_cnt3[N_NODES + ss[k]], 1);
            if (pos < CAP) g_colc[((size_t)ss[k] << CAP_LOG) + pos] = dd[k];
            atomicAdd(&g_cnt3[2 * N_NODES + dd[k]], 1);    // total scatter in-degree
        }
    }
}

// ---------------- layer-0: project p0/s0 per node + scatter p0 along out-edges ----------------
__global__ void __launch_bounds__(256)
k_proj0(const float* __restrict__ x,
        const float* __restrict__ Wl1, const float* __restrict__ Wr1,
        const float* __restrict__ b1,
        float* __restrict__ p0, float* __restrict__ s0,
        float* __restrict__ acc) {
    __shared__ float sW[105];                 // Wl1(50) | Wr1(50) | b1(5)
    int t = threadIdx.x;
    if (t < 50)       sW[t] = Wl1[t];
    else if (t < 100) sW[t] = Wr1[t - 50];
    else if (t < 105) sW[t] = b1[t - 100];
    __syncthreads();

    int warp = t >> 5, lane = t & 31;
    int i = blockIdx.x * 8 + warp;
    if (i >= N_NODES) return;

    float w = 0.f;
    if (lane < 5) {
        float a = 0.f;
        #pragma unroll
        for (int j = 0; j < 10; j++) a = fmaf(sW[lane * 10 + j], __ldg(x + (size_t)i * 10 + j), a);
        w = a;
    } else if (lane >= 8 && lane < 13) {
        int dd = lane - 8;
        float a = sW[100 + dd];
        #pragma unroll
        for (int j = 0; j < 10; j++) a = fmaf(sW[50 + dd * 10 + j], __ldg(x + (size_t)i * 10 + j), a);
        w = a;
    }
    if (lane < 8)               p0[(size_t)i * 8 + lane]       = (lane < 5) ? w : 0.f;
    if (lane >= 8 && lane < 13) s0[(size_t)i * 8 + (lane - 8)] = w;

    float pv0 = __shfl_sync(FULL, w, 0), pv1 = __shfl_sync(FULL, w, 1);
    float pv2 = __shfl_sync(FULL, w, 2), pv3 = __shfl_sync(FULL, w, 3);
    float pv4 = __shfl_sync(FULL, w, 4);

    int cout_i = min(__ldg(g_cnt3 + N_NODES + i), CAP);
    size_t cb = (size_t)i << CAP_LOG;
    for (int j = lane; j < cout_i; j += 32) {
        int dst = __ldg(g_colc + cb + j);
        float* a = acc + (size_t)dst * 8;
        red_add_v4(a, pv0, pv1, pv2, pv3);
        red_add_f32(a + 4, pv4);
    }
}

// ---------------- fused 5-dim layer, TWO nodes per warp: gather + acc_in, scatter p_next ----------------
template<int POUT>
__global__ void __launch_bounds__(256)
k_agg5(const float* __restrict__ p, const float* __restrict__ self,
       const float* __restrict__ acc_in, float* __restrict__ acc_out,
       float* __restrict__ pout, float* __restrict__ sout,
       const float* __restrict__ Wl, const float* __restrict__ Wr,
       const float* __restrict__ b) {
    __shared__ float sWl[POUT * 5], sWr[POUT * 5], sb[POUT];
    int t = threadIdx.x;
    if (t < POUT * 5)                 sWl[t]      = Wl[t];
    if (t >= 32 && t < 32 + POUT * 5) sWr[t - 32] = Wr[t - 32];
    if (t >= 64 && t < 64 + POUT)     sb[t - 64]  = b[t - 64];
    __syncthreads();

    int warp = t >> 5, lane = t & 31;
    int i0 = (blockIdx.x * (blockDim.x >> 5) + warp) * 2;
    if (i0 >= N_NODES) return;

    int2 cin = *reinterpret_cast<const int2*>(g_cnt3 + i0);               // gather in-deg
    int2 csd = *reinterpret_cast<const int2*>(g_cnt3 + 2 * N_NODES + i0); // scatter in-deg
    int degA = min(cin.x, CAP), degB = min(cin.y, CAP);
    int startA = i0 << CAP_LOG, startB = (i0 + 1) << CAP_LOG;
    int endA = startA + degA, endB = startB + degB;

    int half = lane & 1;                   // 0: p[0..3], 1: p[4..7]
    int epos = lane >> 1;                  // edge slot 0..15

    float4 accA = make_float4(0.f, 0.f, 0.f, 0.f);
    float4 accB = make_float4(0.f, 0.f, 0.f, 0.f);
    int jA = startA + epos, jB = startB + epos;
    while (jA < endA || jB < endB) {
        int sA = (jA < endA) ? __ldg(g_col + jA) : -1;
        int sB = (jB < endB) ? __ldg(g_col + jB) : -1;
        if (sA >= 0) {
            float4 v = __ldg(reinterpret_cast<const float4*>(p + (size_t)sA * 8) + half);
            accA.x += v.x; accA.y += v.y; accA.z += v.z; accA.w += v.w;
        }
        if (sB >= 0) {
            float4 v = __ldg(reinterpret_cast<const float4*>(p + (size_t)sB * 8) + half);
            accB.x += v.x; accB.y += v.y; accB.z += v.z; accB.w += v.w;
        }
        jA += 16; jB += 16;
    }

    #pragma unroll
    for (int off = 2; off < 32; off <<= 1) {
        accA.x += __shfl_xor_sync(FULL, accA.x, off);
        accA.y += __shfl_xor_sync(FULL, accA.y, off);
        accA.z += __shfl_xor_sync(FULL, accA.z, off);
        accA.w += __shfl_xor_sync(FULL, accA.w, off);
        accB.x += __shfl_xor_sync(FULL, accB.x, off);
        accB.y += __shfl_xor_sync(FULL, accB.y, off);
        accB.z += __shfl_xor_sync(FULL, accB.z, off);
        accB.w += __shfl_xor_sync(FULL, accB.w, off);
    }

    int h    = lane >> 4;                  // which node this half-warp finishes
    int l16  = lane & 15;
    int base = lane & 16;
    int i    = i0 + h;
    int degT = (h ? cin.y : cin.x) + (h ? csd.y : csd.x);
    float4 acc;
    acc.x = h ? accB.x : accA.x;
    acc.y = h ? accB.y : accA.y;
    acc.z = h ? accB.z : accA.z;
    acc.w = h ? accB.w : accA.w;

    float s0 = __shfl_sync(FULL, acc.x, base);       // even lane: dims0-3
    float s1 = __shfl_sync(FULL, acc.y, base);
    float s2 = __shfl_sync(FULL, acc.z, base);
    float s3 = __shfl_sync(FULL, acc.w, base);
    float s4 = __shfl_sync(FULL, acc.x, base | 1);   // odd lane: dim4

    float inv = 1.0f / (float)max(degT, 1);
    float sv  = (l16 < 5) ? __ldg(self   + (size_t)i * 8 + l16) : 0.f;
    float av  = (l16 < 5) ? __ldg(acc_in + (size_t)i * 8 + l16) : 0.f;

    float f0 = fmaxf(fmaf(s0 + __shfl_sync(FULL, av, base + 0), inv, __shfl_sync(FULL, sv, base + 0)), 0.f);
    float f1 = fmaxf(fmaf(s1 + __shfl_sync(FULL, av, base + 1), inv, __shfl_sync(FULL, sv, base + 1)), 0.f);
    float f2 = fmaxf(fmaf(s2 + __shfl_sync(FULL, av, base + 2), inv, __shfl_sync(FULL, sv, base + 2)), 0.f);
    float f3 = fmaxf(fmaf(s3 + __shfl_sync(FULL, av, base + 3), inv, __shfl_sync(FULL, sv, base + 3)), 0.f);
    float f4 = fmaxf(fmaf(s4 + __shfl_sync(FULL, av, base + 4), inv, __shfl_sync(FULL, sv, base + 4)), 0.f);

    float w = 0.f;
    if (POUT == 5) {
        if (l16 < 5) {
            const float* r = sWl + l16 * 5;
            w = fmaf(r[0], f0, fmaf(r[1], f1, fmaf(r[2], f2, fmaf(r[3], f3, r[4] * f4))));
        } else if (l16 >= 8 && l16 < 13) {
            int dd = l16 - 8;
            const float* r = sWr + dd * 5;
            w = fmaf(r[0], f0, fmaf(r[1], f1, fmaf(r[2], f2, fmaf(r[3], f3,
                fmaf(r[4], f4, sb[dd])))));
        }
        if (l16 < 8)               pout[(size_t)i * 8 + l16]       = (l16 < 5) ? w : 0.f;
        if (l16 >= 8 && l16 < 13)  sout[(size_t)i * 8 + (l16 - 8)] = w;

        // scatter p_next along this node's out-edges into acc_out
        float pv0 = __shfl_sync(FULL, w, base + 0), pv1 = __shfl_sync(FULL, w, base + 1);
        float pv2 = __shfl_sync(FULL, w, base + 2), pv3 = __shfl_sync(FULL, w, base + 3);
        float pv4 = __shfl_sync(FULL, w, base + 4);
        int cout_i = min(__ldg(g_cnt3 + N_NODES + i), CAP);
        size_t cb = (size_t)i << CAP_LOG;
        for (int j = l16; j < cout_i; j += 16) {
            int dst = __ldg(g_colc + cb + j);
            float* a = acc_out + (size_t)dst * 8;
            red_add_v4(a, pv0, pv1, pv2, pv3);
            red_add_f32(a + 4, pv4);
        }
    } else { // POUT == 1: scalar p9/self9; scatter scalar into acc9
        if (l16 == 0) {
            w = fmaf(sWl[0], f0, fmaf(sWl[1], f1, fmaf(sWl[2], f2,
                fmaf(sWl[3], f3, sWl[4] * f4))));
            pout[i] = w;
        } else if (l16 == 1) {
            float ws = fmaf(sWr[0], f0, fmaf(sWr[1], f1, fmaf(sWr[2], f2,
                       fmaf(sWr[3], f3, fmaf(sWr[4], f4, sb[0])))));
            sout[i] = ws;
        }
        float pv = __shfl_sync(FULL, w, base + 0);
        int cout_i = min(__ldg(g_cnt3 + N_NODES + i), CAP);
        size_t cb = (size_t)i << CAP_LOG;
        for (int j = l16; j < cout_i; j += 16)
            red_add_f32(acc_out + __ldg(g_colc + cb + j), pv);
    }
}

// ---------------- final scalar layer: out = (gather + acc9) * inv + self ----------------
__global__ void __launch_bounds__(256)
k_agg_final(const float* __restrict__ p, const float* __restrict__ self,
            const float* __restrict__ acc9, float* __restrict__ out) {
    int t = threadIdx.x;
    int warp = t >> 5, lane = t & 31;
    int h = lane >> 4, l16 = lane & 15;
    int i = (blockIdx.x * (blockDim.x >> 5) + warp) * 2 + h;
    if (i - h >= N_NODES) return;

    int cin = __ldg(g_cnt3 + i);
    int deg = min(cin, CAP);
    int start = i << CAP_LOG, end = start + deg;
    float acc = 0.f;
    for (int j = start + l16; j < end; j += 16)
        acc += __ldg(p + __ldg(g_col + j));
    #pragma unroll
    for (int off = 1; off < 16; off <<= 1)
        acc += __shfl_xor_sync(FULL, acc, off);
    if (l16 == 0) {
        int degT = cin + __ldg(g_cnt3 + 2 * N_NODES + i);
        float inv = 1.0f / (float)max(degT, 1);
        out[i] = fmaf(acc + __ldg(acc9 + i), inv, __ldg(self + i));
    }
}

// ---------------- launch ----------------
extern "C" void kernel_launch(void* const* d_in, const int* in_sizes, int n_in,
                              void* d_out, int out_size) {
    const float* x    = (const float*)d_in[0];
    const int*   ei   = (const int*)  d_in[1];
    const float* Wl1  = (const float*)d_in[2];
    const float* Wr1  = (const float*)d_in[3];
    const float* b1   = (const float*)d_in[4];
    const float* Wlm  = (const float*)d_in[5];   // [8,5,5]
    const float* Wrm  = (const float*)d_in[6];   // [8,5,5]
    const float* bm   = (const float*)d_in[7];   // [8,5]
    const float* Wl10 = (const float*)d_in[8];   // [1,5]
    const float* Wr10 = (const float*)d_in[9];   // [1,5]
    const float* b10  = (const float*)d_in[10];  // [1]
    float* out = (float*)d_out;

    void *pa, *pb, *sa, *sb_, *pcnt, *pac0, *pac1, *pac9;
    cudaGetSymbolAddress(&pa,   g_pa);
    cudaGetSymbolAddress(&pb,   g_pb);
    cudaGetSymbolAddress(&sa,   g_sa);
    cudaGetSymbolAddress(&sb_,  g_sb);
    cudaGetSymbolAddress(&pcnt, g_cnt3);
    cudaGetSymbolAddress(&pac0, g_acc0);
    cudaGetSymbolAddress(&pac1, g_acc1);
    cudaGetSymbolAddress(&pac9, g_acc9);
    float* P[2]   = { (float*)pa,   (float*)pb  };
    float* S[2]   = { (float*)sa,   (float*)sb_ };
    float* ACC[2] = { (float*)pac0, (float*)pac1 };
    float* A9     = (float*)pac9;

    const int E = N_EDGES;
    int e4blocks = (E / 4 + 255) / 256;
    int nb8      = (N_NODES + 7) / 8;       // warp per node
    int npairs   = N_NODES / 2;
    int ablocks  = (npairs + 7) / 8;        // 2 nodes per warp

    const size_t ACC_BYTES = (size_t)N_NODES * 8 * sizeof(float);

    cudaMemsetAsync(pcnt, 0, 3 * N_NODES * sizeof(int));
    k_fill<<<e4blocks, 256>>>(ei, E);

    cudaMemsetAsync(ACC[0], 0, ACC_BYTES);
    k_proj0<<<nb8, 256>>>(x, Wl1, Wr1, b1, P[0], S[0], ACC[0]);   // scatters p0 -> ACC[0]

    // K_L (L=0..7): reads ACC[L&1], scatters p_{L+1} -> ACC[(L+1)&1]
    int cur = 0;
    for (int L = 0; L <= 7; ++L) {
        cudaMemsetAsync(ACC[(L + 1) & 1], 0, ACC_BYTES);
        k_agg5<5><<<ablocks, 256>>>(P[cur], S[cur], ACC[L & 1], ACC[(L + 1) & 1],
                                    P[1 - cur], S[1 - cur],
                                    Wlm + L * 25, Wrm + L * 25, bm + L * 5);
        cur = 1 - cur;
    }
    // K_8: reads ACC[0], scatters scalar p9 -> acc9
    cudaMemsetAsync(A9, 0, N_NODES * sizeof(float));
    k_agg5<1><<<ablocks, 256>>>(P[cur], S[cur], ACC[0], A9,
                                P[1 - cur], S[1 - cur], Wl10, Wr10, b10);
    cur = 1 - cur;
    // final: out = (gather(p9) + acc9) * inv + self9
    k_agg_final<<<ablocks, 256>>>(P[cur], S[cur], A9, out);
}

// round 9
// speedup vs baseline: 1.0869x; 1.0869x over previous
#include <cuda_runtime.h>

#define N_NODES 500000
#define N_EDGES 16000000
#define FULL 0xffffffffu
#define CAP_LOG 7                              // 128 slots per node bucket
#define CAP (1 << CAP_LOG)

// ---------------- device scratch (static; no allocation) ----------------
__device__ int   g_cnt[N_NODES];               // in-degree (also fill cursor)
__device__ int   g_col[(size_t)N_NODES * CAP]; // bucketized CSR: row i at i*CAP
__device__ float g_pa[(size_t)N_NODES * 8];    // projected features (32B records)
__device__ float g_pb[(size_t)N_NODES * 8];
__device__ float g_sa[(size_t)N_NODES * 8];    // precomputed self terms
__device__ float g_sb[(size_t)N_NODES * 8];

// ---------------- fused build: CSR fill (blocks [0,nfill)) + layer-0 proj (rest) ----------------
__global__ void __launch_bounds__(256)
k_build(const int* __restrict__ ei, int E, int nfill,
        const float* __restrict__ x,
        const float* __restrict__ Wl1, const float* __restrict__ Wr1,
        const float* __restrict__ b1,
        float* __restrict__ p0, float* __restrict__ s0) {
    if (blockIdx.x < nfill) {
        int e4 = (blockIdx.x * blockDim.x + threadIdx.x) * 4;
        if (e4 < E) {
            int4 d = *reinterpret_cast<const int4*>(ei + E + e4);  // dst
            int4 s = *reinterpret_cast<const int4*>(ei + e4);      // src
            int q0 = atomicAdd(&g_cnt[d.x], 1); g_col[((size_t)d.x << CAP_LOG) + q0] = s.x;
            int q1 = atomicAdd(&g_cnt[d.y], 1); g_col[((size_t)d.y << CAP_LOG) + q1] = s.y;
            int q2 = atomicAdd(&g_cnt[d.z], 1); g_col[((size_t)d.z << CAP_LOG) + q2] = s.z;
            int q3 = atomicAdd(&g_cnt[d.w], 1); g_col[((size_t)d.w << CAP_LOG) + q3] = s.w;
        }
        return;
    }
    // ---- projection part ----
    __shared__ float sW[105];                 // Wl1(50) | Wr1(50) | b1(5)
    int t = threadIdx.x;
    if (t < 50)       sW[t] = Wl1[t];
    else if (t < 100) sW[t] = Wr1[t - 50];
    else if (t < 105) sW[t] = b1[t - 100];
    __syncthreads();

    int i = (blockIdx.x - nfill) * blockDim.x + t;
    if (i >= N_NODES) return;

    float xv[10];
    #pragma unroll
    for (int j = 0; j < 10; j++) xv[j] = x[(size_t)i * 10 + j];

    float pv[5], sv[5];
    #pragma unroll
    for (int d = 0; d < 5; d++) {
        float a = 0.f, bsum = sW[100 + d];
        #pragma unroll
        for (int j = 0; j < 10; j++) {
            a    = fmaf(sW[d * 10 + j],      xv[j], a);
            bsum = fmaf(sW[50 + d * 10 + j], xv[j], bsum);
        }
        pv[d] = a; sv[d] = bsum;
    }
    float4* pr = reinterpret_cast<float4*>(p0 + (size_t)i * 8);
    float4* sr = reinterpret_cast<float4*>(s0 + (size_t)i * 8);
    pr[0] = make_float4(pv[0], pv[1], pv[2], pv[3]);
    pr[1] = make_float4(pv[4], 0.f, 0.f, 0.f);
    sr[0] = make_float4(sv[0], sv[1], sv[2], sv[3]);
    sr[1] = make_float4(sv[4], 0.f, 0.f, 0.f);
}

// ---------------- k=4 gather: 8 lanes per record, 4 edges per LDG.32 ----------------
// lane reads float (lane&7) of record for edge-slot (lane>>3); pad dims 5-7 are
// zero so the read is harmless. col indices preloaded coalesced (1 line / 32
// edges), distributed with 1 shfl per 4 edges. Returns per-lane partial for dim
// (lane&7); caller reduces with shfl-xor 8,16.
__device__ __forceinline__ float gather_k4(const float* __restrict__ p,
                                           int start, int end, int lane) {
    int g = lane >> 3;        // edge slot within 4-group
    int d = lane & 7;         // dim slot
    float acc = 0.f;
    for (int jb = start; jb < end; jb += 32) {
        int cj = jb + lane;
        int c  = (cj < end) ? __ldg(g_col + cj) : 0;
        int n  = end - jb;
        #pragma unroll
        for (int it = 0; it < 8; ++it) {
            int e = it * 4 + g;
            int s = __shfl_sync(FULL, c, e);
            if (e < n) acc += __ldg(p + (size_t)s * 8 + d);
        }
    }
    return acc;
}

// ---------------- fused 5-dim layer, two nodes per warp ----------------
template<int POUT>
__global__ void __launch_bounds__(256)
k_agg5(const float* __restrict__ p, const float* __restrict__ self,
       float* __restrict__ pout, float* __restrict__ sout,
       const float* __restrict__ Wl, const float* __restrict__ Wr,
       const float* __restrict__ b) {
    __shared__ float sWl[POUT * 5], sWr[POUT * 5], sb[POUT];
    int t = threadIdx.x;
    if (t < POUT * 5)                 sWl[t]      = Wl[t];
    if (t >= 32 && t < 32 + POUT * 5) sWr[t - 32] = Wr[t - 32];
    if (t >= 64 && t < 64 + POUT)     sb[t - 64]  = b[t - 64];
    __syncthreads();

    int warp = t >> 5, lane = t & 31;
    int i0 = (blockIdx.x * (blockDim.x >> 5) + warp) * 2;
    if (i0 >= N_NODES) return;

    int2 dg = *reinterpret_cast<const int2*>(g_cnt + i0);   // degA, degB
    int degA = dg.x, degB = dg.y;
    int startA = i0 << CAP_LOG, startB = (i0 + 1) << CAP_LOG;

    float accA = gather_k4(p, startA, startA + degA, lane);
    float accB = gather_k4(p, startB, startB + degB, lane);

    // sum the 4 edge-groups: lanes {l, l^8, l^16, l^24} hold same dim
    accA += __shfl_xor_sync(FULL, accA, 8);
    accA += __shfl_xor_sync(FULL, accA, 16);
    accB += __shfl_xor_sync(FULL, accB, 8);
    accB += __shfl_xor_sync(FULL, accB, 16);

    int h    = lane >> 4;                  // which node this half-warp finishes
    int l16  = lane & 15;
    int base = lane & 16;
    int i    = i0 + h;
    int deg  = h ? degB : degA;
    float acc = h ? accB : accA;

    float s0 = __shfl_sync(FULL, acc, base + 0);
    float s1 = __shfl_sync(FULL, acc, base + 1);
    float s2 = __shfl_sync(FULL, acc, base + 2);
    float s3 = __shfl_sync(FULL, acc, base + 3);
    float s4 = __shfl_sync(FULL, acc, base + 4);

    float inv = 1.0f / (float)max(deg, 1);
    float sv  = (l16 < 5) ? __ldg(self + (size_t)i * 8 + l16) : 0.f;

    float f0 = fmaxf(fmaf(s0, inv, __shfl_sync(FULL, sv, base + 0)), 0.f);
    float f1 = fmaxf(fmaf(s1, inv, __shfl_sync(FULL, sv, base + 1)), 0.f);
    float f2 = fmaxf(fmaf(s2, inv, __shfl_sync(FULL, sv, base + 2)), 0.f);
    float f3 = fmaxf(fmaf(s3, inv, __shfl_sync(FULL, sv, base + 3)), 0.f);
    float f4 = fmaxf(fmaf(s4, inv, __shfl_sync(FULL, sv, base + 4)), 0.f);

    if (POUT == 5) {
        if (l16 < 8) {
            float w = 0.f;
            if (l16 < 5) {
                const float* r = sWl + l16 * 5;
                w = fmaf(r[0], f0, fmaf(r[1], f1, fmaf(r[2], f2, fmaf(r[3], f3, r[4] * f4))));
            }
            pout[(size_t)i * 8 + l16] = w;   // lanes 5-7 keep pads zero
        }
        if (l16 >= 8 && l16 < 13) {
            int d = l16 - 8;
            const float* r = sWr + d * 5;
            float w = fmaf(r[0], f0, fmaf(r[1], f1, fmaf(r[2], f2, fmaf(r[3], f3,
                      fmaf(r[4], f4, sb[d])))));
            sout[(size_t)i * 8 + d] = w;
        }
    } else { // POUT == 1: scalar p_next / self_next (stride 1)
        if (l16 == 0) {
            float w = fmaf(sWl[0], f0, fmaf(sWl[1], f1, fmaf(sWl[2], f2,
                      fmaf(sWl[3], f3, sWl[4] * f4))));
            pout[i] = w;
        }
        if (l16 == 1) {
            float w = fmaf(sWr[0], f0, fmaf(sWr[1], f1, fmaf(sWr[2], f2,
                      fmaf(sWr[3], f3, fmaf(sWr[4], f4, sb[0])))));
            sout[i] = w;
        }
    }
}

// ---------------- final scalar layer, two nodes per warp (round-6 proven) ----------------
__global__ void __launch_bounds__(256)
k_agg_final(const float* __restrict__ p, const float* __restrict__ self,
            float* __restrict__ out) {
    int t = threadIdx.x;
    int warp = t >> 5, lane = t & 31;
    int h = lane >> 4, l16 = lane & 15;
    int i = (blockIdx.x * (blockDim.x >> 5) + warp) * 2 + h;
    if (i - h >= N_NODES) return;

    int deg = g_cnt[i];
    int start = i << CAP_LOG, end = start + deg;
    float acc = 0.f;
    for (int j = start + l16; j < end; j += 16)
        acc += __ldg(p + __ldg(g_col + j));
    #pragma unroll
    for (int off = 1; off < 16; off <<= 1)
        acc += __shfl_xor_sync(FULL, acc, off);
    if (l16 == 0) {
        float inv = 1.0f / (float)max(deg, 1);
        out[i] = fmaf(acc, inv, __ldg(self + i));
    }
}

// ---------------- launch ----------------
extern "C" void kernel_launch(void* const* d_in, const int* in_sizes, int n_in,
                              void* d_out, int out_size) {
    const float* x    = (const float*)d_in[0];
    const int*   ei   = (const int*)  d_in[1];
    const float* Wl1  = (const float*)d_in[2];
    const float* Wr1  = (const float*)d_in[3];
    const float* b1   = (const float*)d_in[4];
    const float* Wlm  = (const float*)d_in[5];   // [8,5,5]
    const float* Wrm  = (const float*)d_in[6];   // [8,5,5]
    const float* bm   = (const float*)d_in[7];   // [8,5]
    const float* Wl10 = (const float*)d_in[8];   // [1,5]
    const float* Wr10 = (const float*)d_in[9];   // [1,5]
    const float* b10  = (const float*)d_in[10];  // [1]
    float* out = (float*)d_out;

    void *pa, *pb, *sa, *sb_, *pcnt;
    cudaGetSymbolAddress(&pa,   g_pa);
    cudaGetSymbolAddress(&pb,   g_pb);
    cudaGetSymbolAddress(&sa,   g_sa);
    cudaGetSymbolAddress(&sb_,  g_sb);
    cudaGetSymbolAddress(&pcnt, g_cnt);
    float* P[2] = { (float*)pa,  (float*)pb  };
    float* S[2] = { (float*)sa,  (float*)sb_ };

    const int E = N_EDGES;
    int e4blocks = (E / 4 + 255) / 256;      // fill blocks
    int nb       = (N_NODES + 255) / 256;    // proj blocks
    int npairs   = N_NODES / 2;
    int ablocks  = (npairs + 7) / 8;         // 2 nodes per warp, 8 warps/block

    cudaMemsetAsync(pcnt, 0, N_NODES * sizeof(int));
    k_build<<<e4blocks + nb, 256>>>(ei, E, e4blocks, x, Wl1, Wr1, b1, P[0], S[0]);

    // layers 0..7
    int cur = 0;
    for (int L = 0; L <= 7; ++L) {
        k_agg5<5><<<ablocks, 256>>>(P[cur], S[cur], P[1 - cur], S[1 - cur],
                                    Wlm + L * 25, Wrm + L * 25, bm + L * 5);
        cur = 1 - cur;
    }
    // layer 8: pre-project scalar p9/self9 with Wl10/Wr10/b10
    k_agg5<1><<<ablocks, 256>>>(P[cur], S[cur], P[1 - cur], S[1 - cur],
                                Wl10, Wr10, b10);
    cur = 1 - cur;
    // layer 9 (final, no relu): out = mean(p9) + self9
    k_agg_final<<<ablocks, 256>>>(P[cur], S[cur], out);
}

// round 10
// speedup vs baseline: 1.4255x; 1.3115x over previous
#include <cuda_runtime.h>

#define N_NODES 500000
#define N_EDGES 16000000
#define FULL 0xffffffffu
#define CAP_LOG 7                              // 128 slots per node bucket
#define CAP (1 << CAP_LOG)

// ---------------- device scratch (static; no allocation) ----------------
__device__ int   g_cnt[N_NODES];               // in-degree (also fill cursor)
__device__ int   g_col[(size_t)N_NODES * CAP]; // bucketized CSR: row i at i*CAP
__device__ float g_pa[(size_t)N_NODES * 8];    // projected features (32B records)
__device__ float g_pb[(size_t)N_NODES * 8];
__device__ float g_sa[(size_t)N_NODES * 8];    // precomputed self terms
__device__ float g_sb[(size_t)N_NODES * 8];

// ---------------- fused build: CSR fill (blocks [0,nfill)) + layer-0 proj (rest) ----------------
__global__ void __launch_bounds__(256)
k_build(const int* __restrict__ ei, int E, int nfill,
        const float* __restrict__ x,
        const float* __restrict__ Wl1, const float* __restrict__ Wr1,
        const float* __restrict__ b1,
        float* __restrict__ p0, float* __restrict__ s0) {
    if (blockIdx.x < nfill) {
        int e4 = (blockIdx.x * blockDim.x + threadIdx.x) * 4;
        if (e4 < E) {
            int4 d = *reinterpret_cast<const int4*>(ei + E + e4);  // dst
            int4 s = *reinterpret_cast<const int4*>(ei + e4);      // src
            int q0 = atomicAdd(&g_cnt[d.x], 1); g_col[((size_t)d.x << CAP_LOG) + q0] = s.x;
            int q1 = atomicAdd(&g_cnt[d.y], 1); g_col[((size_t)d.y << CAP_LOG) + q1] = s.y;
            int q2 = atomicAdd(&g_cnt[d.z], 1); g_col[((size_t)d.z << CAP_LOG) + q2] = s.z;
            int q3 = atomicAdd(&g_cnt[d.w], 1); g_col[((size_t)d.w << CAP_LOG) + q3] = s.w;
        }
        return;
    }
    // ---- layer-0 projection part ----
    __shared__ float sW[105];                 // Wl1(50) | Wr1(50) | b1(5)
    int t = threadIdx.x;
    if (t < 50)       sW[t] = Wl1[t];
    else if (t < 100) sW[t] = Wr1[t - 50];
    else if (t < 105) sW[t] = b1[t - 100];
    __syncthreads();

    int i = (blockIdx.x - nfill) * blockDim.x + t;
    if (i >= N_NODES) return;

    float xv[10];
    #pragma unroll
    for (int j = 0; j < 10; j++) xv[j] = x[(size_t)i * 10 + j];

    float pv[5], sv[5];
    #pragma unroll
    for (int d = 0; d < 5; d++) {
        float a = 0.f, bsum = sW[100 + d];
        #pragma unroll
        for (int j = 0; j < 10; j++) {
            a    = fmaf(sW[d * 10 + j],      xv[j], a);
            bsum = fmaf(sW[50 + d * 10 + j], xv[j], bsum);
        }
        pv[d] = a; sv[d] = bsum;
    }
    float4* pr = reinterpret_cast<float4*>(p0 + (size_t)i * 8);
    float4* sr = reinterpret_cast<float4*>(s0 + (size_t)i * 8);
    pr[0] = make_float4(pv[0], pv[1], pv[2], pv[3]);
    pr[1] = make_float4(pv[4], 0.f, 0.f, 0.f);
    sr[0] = make_float4(sv[0], sv[1], sv[2], sv[3]);
    sr[1] = make_float4(sv[4], 0.f, 0.f, 0.f);
}

// ---------------- fused 5-dim layer, TWO nodes per warp ----------------
// Gather (round-6, at the L1tex replay floor): lane pairs load float4 halves
// of a node's 32B record; 2x unrolled so 4 gather LDGs are in flight per warp.
// Reduce: fold halves (xor16), SELECT this half-warp's node, 3 parity levels.
template<int POUT>
__global__ void __launch_bounds__(256)
k_agg5(const float* __restrict__ p, const float* __restrict__ self,
       float* __restrict__ pout, float* __restrict__ sout,
       const float* __restrict__ Wl, const float* __restrict__ Wr,
       const float* __restrict__ b) {
    __shared__ float sWl[POUT * 5], sWr[POUT * 5], sb[POUT];
    int t = threadIdx.x;
    if (t < POUT * 5)                 sWl[t]      = Wl[t];
    if (t >= 32 && t < 32 + POUT * 5) sWr[t - 32] = Wr[t - 32];
    if (t >= 64 && t < 64 + POUT)     sb[t - 64]  = b[t - 64];
    __syncthreads();

    int warp = t >> 5, lane = t & 31;
    int i0 = (blockIdx.x * (blockDim.x >> 5) + warp) * 2;
    if (i0 >= N_NODES) return;

    int2 dg = *reinterpret_cast<const int2*>(g_cnt + i0);   // degA, degB (i0 even)
    int degA = dg.x, degB = dg.y;
    int startA = i0 << CAP_LOG, startB = (i0 + 1) << CAP_LOG;
    int endA = startA + degA, endB = startB + degB;

    int half = lane & 1;                   // 0: p[0..3], 1: p[4..7]
    int epos = lane >> 1;                  // edge slot 0..15

    float4 accA = make_float4(0.f, 0.f, 0.f, 0.f);
    float4 accB = make_float4(0.f, 0.f, 0.f, 0.f);
    int jA = startA + epos, jB = startB + epos;
    while (jA < endA || jB < endB) {
        int sA0 = (jA      < endA) ? __ldg(g_col + jA)      : -1;
        int sA1 = (jA + 16 < endA) ? __ldg(g_col + jA + 16) : -1;
        int sB0 = (jB      < endB) ? __ldg(g_col + jB)      : -1;
        int sB1 = (jB + 16 < endB) ? __ldg(g_col + jB + 16) : -1;
        if (sA0 >= 0) {
            float4 v = __ldg(reinterpret_cast<const float4*>(p + (size_t)sA0 * 8) + half);
            accA.x += v.x; accA.y += v.y; accA.z += v.z; accA.w += v.w;
        }
        if (sB0 >= 0) {
            float4 v = __ldg(reinterpret_cast<const float4*>(p + (size_t)sB0 * 8) + half);
            accB.x += v.x; accB.y += v.y; accB.z += v.z; accB.w += v.w;
        }
        if (sA1 >= 0) {
            float4 v = __ldg(reinterpret_cast<const float4*>(p + (size_t)sA1 * 8) + half);
            accA.x += v.x; accA.y += v.y; accA.z += v.z; accA.w += v.w;
        }
        if (sB1 >= 0) {
            float4 v = __ldg(reinterpret_cast<const float4*>(p + (size_t)sB1 * 8) + half);
            accB.x += v.x; accB.y += v.y; accB.z += v.z; accB.w += v.w;
        }
        jA += 32; jB += 32;
    }

    // fold across halves (xor 16 preserves lane parity)
    accA.x += __shfl_xor_sync(FULL, accA.x, 16);
    accA.y += __shfl_xor_sync(FULL, accA.y, 16);
    accA.z += __shfl_xor_sync(FULL, accA.z, 16);
    accA.w += __shfl_xor_sync(FULL, accA.w, 16);
    accB.x += __shfl_xor_sync(FULL, accB.x, 16);
    accB.y += __shfl_xor_sync(FULL, accB.y, 16);
    accB.z += __shfl_xor_sync(FULL, accB.z, 16);
    accB.w += __shfl_xor_sync(FULL, accB.w, 16);

    int h    = lane >> 4;                  // which node this half-warp finishes
    int l16  = lane & 15;
    int base = lane & 16;
    int i    = i0 + h;
    int deg  = h ? degB : degA;

    // select this half-warp's node, then 3 parity-preserving levels
    float4 u;
    u.x = h ? accB.x : accA.x;
    u.y = h ? accB.y : accA.y;
    u.z = h ? accB.z : accA.z;
    u.w = h ? accB.w : accA.w;
    #pragma unroll
    for (int off = 2; off <= 8; off <<= 1) {
        u.x += __shfl_xor_sync(FULL, u.x, off);
        u.y += __shfl_xor_sync(FULL, u.y, off);
        u.z += __shfl_xor_sync(FULL, u.z, off);
        u.w += __shfl_xor_sync(FULL, u.w, off);
    }

    float s0 = __shfl_sync(FULL, u.x, base);         // even lane: dims0-3
    float s1 = __shfl_sync(FULL, u.y, base);
    float s2 = __shfl_sync(FULL, u.z, base);
    float s3 = __shfl_sync(FULL, u.w, base);
    float s4 = __shfl_sync(FULL, u.x, base | 1);     // odd lane: dim4

    float inv = 1.0f / (float)max(deg, 1);
    float sv  = (l16 < 5) ? __ldg(self + (size_t)i * 8 + l16) : 0.f;

    float f0 = fmaxf(fmaf(s0, inv, __shfl_sync(FULL, sv, base + 0)), 0.f);
    float f1 = fmaxf(fmaf(s1, inv, __shfl_sync(FULL, sv, base + 1)), 0.f);
    float f2 = fmaxf(fmaf(s2, inv, __shfl_sync(FULL, sv, base + 2)), 0.f);
    float f3 = fmaxf(fmaf(s3, inv, __shfl_sync(FULL, sv, base + 3)), 0.f);
    float f4 = fmaxf(fmaf(s4, inv, __shfl_sync(FULL, sv, base + 4)), 0.f);

    if (POUT == 5) {
        if (l16 < 8) {
            float w = 0.f;
            if (l16 < 5) {
                const float* r = sWl + l16 * 5;
                w = fmaf(r[0], f0, fmaf(r[1], f1, fmaf(r[2], f2, fmaf(r[3], f3, r[4] * f4))));
            }
            pout[(size_t)i * 8 + l16] = w;   // lanes 5-7 keep pads zero
        }
        if (l16 >= 8 && l16 < 13) {
            int d = l16 - 8;
            const float* r = sWr + d * 5;
            float w = fmaf(r[0], f0, fmaf(r[1], f1, fmaf(r[2], f2, fmaf(r[3], f3,
                      fmaf(r[4], f4, sb[d])))));
            sout[(size_t)i * 8 + d] = w;
        }
    } else { // POUT == 1: scalar p_next / self_next (stride 1)
        if (l16 == 0) {
            float w = fmaf(sWl[0], f0, fmaf(sWl[1], f1, fmaf(sWl[2], f2,
                      fmaf(sWl[3], f3, sWl[4] * f4))));
            pout[i] = w;
        }
        if (l16 == 1) {
            float w = fmaf(sWr[0], f0, fmaf(sWr[1], f1, fmaf(sWr[2], f2,
                      fmaf(sWr[3], f3, fmaf(sWr[4], f4, sb[0])))));
            sout[i] = w;
        }
    }
}

// ---------------- final scalar layer, two nodes per warp (round-6 proven) ----------------
__global__ void __launch_bounds__(256)
k_agg_final(const float* __restrict__ p, const float* __restrict__ self,
            float* __restrict__ out) {
    int t = threadIdx.x;
    int warp = t >> 5, lane = t & 31;
    int h = lane >> 4, l16 = lane & 15;
    int i = (blockIdx.x * (blockDim.x >> 5) + warp) * 2 + h;
    if (i - h >= N_NODES) return;

    int deg = g_cnt[i];
    int start = i << CAP_LOG, end = start + deg;
    float acc = 0.f;
    for (int j = start + l16; j < end; j += 16)
        acc += __ldg(p + __ldg(g_col + j));
    #pragma unroll
    for (int off = 1; off < 16; off <<= 1)
        acc += __shfl_xor_sync(FULL, acc, off);
    if (l16 == 0) {
        float inv = 1.0f / (float)max(deg, 1);
        out[i] = fmaf(acc, inv, __ldg(self + i));
    }
}

// ---------------- launch ----------------
extern "C" void kernel_launch(void* const* d_in, const int* in_sizes, int n_in,
                              void* d_out, int out_size) {
    const float* x    = (const float*)d_in[0];
    const int*   ei   = (const int*)  d_in[1];
    const float* Wl1  = (const float*)d_in[2];
    const float* Wr1  = (const float*)d_in[3];
    const float* b1   = (const float*)d_in[4];
    const float* Wlm  = (const float*)d_in[5];   // [8,5,5]
    const float* Wrm  = (const float*)d_in[6];   // [8,5,5]
    const float* bm   = (const float*)d_in[7];   // [8,5]
    const float* Wl10 = (const float*)d_in[8];   // [1,5]
    const float* Wr10 = (const float*)d_in[9];   // [1,5]
    const float* b10  = (const float*)d_in[10];  // [1]
    float* out = (float*)d_out;

    void *pa, *pb, *sa, *sb_, *pcnt;
    cudaGetSymbolAddress(&pa,   g_pa);
    cudaGetSymbolAddress(&pb,   g_pb);
    cudaGetSymbolAddress(&sa,   g_sa);
    cudaGetSymbolAddress(&sb_,  g_sb);
    cudaGetSymbolAddress(&pcnt, g_cnt);
    float* P[2] = { (float*)pa,  (float*)pb  };
    float* S[2] = { (float*)sa,  (float*)sb_ };

    const int E = N_EDGES;
    int e4blocks = (E / 4 + 255) / 256;      // fill blocks
    int nb       = (N_NODES + 255) / 256;    // proj blocks
    int npairs   = N_NODES / 2;
    int ablocks  = (npairs + 7) / 8;         // 2 nodes per warp, 8 warps/block

    cudaMemsetAsync(pcnt, 0, N_NODES * sizeof(int));
    k_build<<<e4blocks + nb, 256>>>(ei, E, e4blocks, x, Wl1, Wr1, b1, P[0], S[0]);

    // layers 0..7
    int cur = 0;
    for (int L = 0; L <= 7; ++L) {
        k_agg5<5><<<ablocks, 256>>>(P[cur], S[cur], P[1 - cur], S[1 - cur],
                                    Wlm + L * 25, Wrm + L * 25, bm + L * 5);
        cur = 1 - cur;
    }
    // layer 8: pre-project scalar p9/self9 with Wl10/Wr10/b10
    k_agg5<1><<<ablocks, 256>>>(P[cur], S[cur], P[1 - cur], S[1 - cur],
                                Wl10, Wr10, b10);
    cur = 1 - cur;
    // layer 9 (final, no relu): out = mean(p9) + self9
    k_agg_final<<<ablocks, 256>>>(P[cur], S[cur], out);
}